// round 14
// baseline (speedup 1.0000x reference)
#include <cuda_runtime.h>
#include <cuda_bf16.h>
#include <math.h>
#include <stdint.h>

// Problem constants
#define BATCH   16
#define NPTS    8192
#define SPTS    1024        // NPOINT
#define KSAMP   32          // NSAMPLE
#define CIN     64          // input point feature channels
#define NROWS   (BATCH*SPTS*KSAMP)   // 524288
#define NGRP    (BATCH*SPTS)         // 16384
#define NTILES  (NROWS/64)           // 8192
#define OUT_XYZ_ELEMS (BATCH*SPTS*3) // 49152
#define NSM     148

typedef unsigned long long u64;

// ---------------- scratch (device globals; no dynamic alloc allowed) -------
__device__ float g_ptsT[(size_t)BATCH*NPTS*CIN];       // 33.5 MB  (B,N,C)
__device__ int   g_gidx[(size_t)BATCH*SPTS*KSAMP];     // ball query indices
__device__ float g_y1[(size_t)NROWS*64];               // 134 MB
__device__ float g_y2[(size_t)NROWS*64];               // 134 MB
__device__ float g_ymax[(size_t)NGRP*128];             // 8 MB (raw max over K)
__device__ float g_stats[512];                         // [L0 sum|sq][L1][L2]
// pre-split weights (tf32 hi/lo pairs), K-major [c][o]
__device__ uint2 g_wsplit[72*64 + 64*64 + 64*128];

// ---------------- helpers ---------------------------------------------------
__device__ __forceinline__ u64 pack2(float lo, float hi) {
    u64 r; asm("mov.b64 %0, {%1,%2};" : "=l"(r) : "f"(lo), "f"(hi)); return r;
}
__device__ __forceinline__ void unpack2(u64 v, float& lo, float& hi) {
    asm("mov.b64 {%0,%1}, %2;" : "=f"(lo), "=f"(hi) : "l"(v));
}
__device__ __forceinline__ u64 add2(u64 a, u64 b) {
    u64 r; asm("add.rn.f32x2 %0, %1, %2;" : "=l"(r) : "l"(a), "l"(b)); return r;
}
__device__ __forceinline__ u64 mul2(u64 a, u64 b) {
    u64 r; asm("mul.rn.f32x2 %0, %1, %2;" : "=l"(r) : "l"(a), "l"(b)); return r;
}
__device__ __forceinline__ u64 fma2(u64 a, u64 b, u64 c) {
    u64 r; asm("fma.rn.f32x2 %0, %1, %2, %3;" : "=l"(r) : "l"(a), "l"(b), "l"(c)); return r;
}
__device__ __forceinline__ unsigned redux_max_u32(unsigned v) {
    unsigned d; asm("redux.sync.max.u32 %0, %1, 0xffffffff;" : "=r"(d) : "r"(v));
    return d;
}
__device__ __forceinline__ unsigned enc_f(float f) {
    unsigned u = __float_as_uint(f);
    return (u & 0x80000000u) ? ~u : (u | 0x80000000u);
}
__device__ __forceinline__ float dec_f(unsigned u) {
    return __uint_as_float((u & 0x80000000u) ? (u & 0x7fffffffu) : ~u);
}
__device__ __forceinline__ void tf32_split(float v, uint32_t& hi, uint32_t& lo) {
    uint32_t h;
    asm("cvt.rna.tf32.f32 %0, %1;" : "=r"(h) : "f"(v));
    float r = v - __uint_as_float(h);
    asm("cvt.rna.tf32.f32 %0, %1;" : "=r"(lo) : "f"(r));
    hi = h;
}
__device__ __forceinline__ void mma16n8k8(float* c, const uint32_t* a,
                                          uint32_t b0, uint32_t b1) {
    asm volatile(
        "mma.sync.aligned.m16n8k8.row.col.f32.tf32.tf32.f32 "
        "{%0,%1,%2,%3}, {%4,%5,%6,%7}, {%8,%9}, {%0,%1,%2,%3};"
        : "+f"(c[0]), "+f"(c[1]), "+f"(c[2]), "+f"(c[3])
        : "r"(a[0]), "r"(a[1]), "r"(a[2]), "r"(a[3]), "r"(b0), "r"(b1));
}

// ---------------- transpose (B,C,N)->(B,N,C) + zero stats + W pre-split -----
__global__ void transpose_points_kernel(const float* __restrict__ pts,
                                        const float* __restrict__ w0,
                                        const float* __restrict__ w1,
                                        const float* __restrict__ w2) {
    __shared__ float tile[32][33];
    int b  = blockIdx.z;
    int n0 = blockIdx.x * 32;
    int c0 = blockIdx.y * 32;
    int tx = threadIdx.x, ty = threadIdx.y;   // 32 x 8
    int tid = ty * 32 + tx;

    if (blockIdx.x == 0 && blockIdx.y == 0 && blockIdx.z == 0) {
        g_stats[tid] = 0.0f;
        g_stats[tid + 256] = 0.0f;
    }
    if (blockIdx.x == 1 && blockIdx.y == 0 && blockIdx.z < 3) {
        int L = blockIdx.z;
        int KIN  = (L == 0) ? 67 : 64;
        int KP   = (L == 0) ? 72 : 64;
        int NOUT = (L == 2) ? 128 : 64;
        int OFF  = (L == 0) ? 0 : (L == 1) ? 72*64 : 72*64 + 64*64;
        const float* W = (L == 0) ? w0 : (L == 1) ? w1 : w2;
        for (int i = tid; i < KP * NOUT; i += 256) {
            int c = i / NOUT, o = i - c * NOUT;
            float v = (c < KIN) ? W[o * KIN + c] : 0.0f;
            uint32_t hi, lo;
            tf32_split(v, hi, lo);
            g_wsplit[OFF + i] = make_uint2(hi, lo);
        }
    }

    #pragma unroll
    for (int i = 0; i < 32; i += 8)
        tile[ty + i][tx] = pts[((size_t)b*CIN + c0 + ty + i) * NPTS + n0 + tx];
    __syncthreads();
    #pragma unroll
    for (int i = 0; i < 32; i += 8)
        g_ptsT[((size_t)b*NPTS + n0 + ty + i) * CIN + c0 + tx] = tile[tx][ty + i];
}

// ---------------- farthest point sampling (1024 thr, 8 pts/thread) ----------
// Same reduction scheme as the measured-best R9 kernel (two barriers, redux
// warp max -> smem -> redux over 32 -> candidate scan + atomicMin), but with
// half the per-warp distance work and 8 warps/SMSP to hide the serial chain.
__global__ void __launch_bounds__(1024, 1)
fps_kernel(const float* __restrict__ xyz, float* __restrict__ out_newxyz) {
    const int b = blockIdx.x;
    const float* X = xyz + (size_t)b * NPTS * 3;
    const int t = threadIdx.x;          // 0..1023
    const int base = t * 8;             // contiguous 8 points per thread

    u64 px2[4], py2[4], pz2[4];
    float dist[8];
    #pragma unroll
    for (int i = 0; i < 4; i++) {
        int p = base + 2 * i;
        float x0 = X[p*3+0], y0 = X[p*3+1], z0 = X[p*3+2];
        float x1 = X[p*3+3], y1 = X[p*3+4], z1 = X[p*3+5];
        px2[i] = pack2(x0, x1);
        py2[i] = pack2(y0, y1);
        pz2[i] = pack2(z0, z1);
        dist[2*i] = 1e10f; dist[2*i+1] = 1e10f;
    }

    __shared__ unsigned s_val[32];
    __shared__ int      s_far2[2];

    int far = 0;
    for (int it = 0; it < SPTS; it++) {
        float cx = X[far*3 + 0];
        float cy = X[far*3 + 1];
        float cz = X[far*3 + 2];
        const int p = it & 1;
        if (t == 0) {
            float* o = out_newxyz + ((size_t)b*SPTS + it) * 3;
            o[0] = cx; o[1] = cy; o[2] = cz;
            s_far2[p] = 0x7fffffff;
        }
        u64 ncx2 = pack2(-cx, -cx);
        u64 ncy2 = pack2(-cy, -cy);
        u64 ncz2 = pack2(-cz, -cz);

        float best = 0.0f;               // dists >= 0
        #pragma unroll
        for (int i = 0; i < 4; i++) {
            u64 dx2 = add2(px2[i], ncx2);
            u64 dy2 = add2(py2[i], ncy2);
            u64 dz2 = add2(pz2[i], ncz2);
            u64 d2 = mul2(dx2, dx2);
            d2 = fma2(dy2, dy2, d2);
            d2 = fma2(dz2, dz2, d2);
            float d0, d1; unpack2(d2, d0, d1);
            float n0 = fminf(dist[2*i],   d0); dist[2*i]   = n0;
            float n1 = fminf(dist[2*i+1], d1); dist[2*i+1] = n1;
            best = fmaxf(best, fmaxf(n0, n1));
        }

        unsigned bb = __float_as_uint(best);   // nonneg -> order-preserving
        unsigned wmax = redux_max_u32(bb);
        if ((t & 31) == 0) s_val[t >> 5] = wmax;
        __syncthreads();

        unsigned gmax = redux_max_u32(s_val[t & 31]);

        if (bb == gmax) {                // candidate holder(s), rare path
            float bv = __uint_as_float(gmax);
            int loc = 0x7fffffff;
            #pragma unroll
            for (int i = 7; i >= 0; --i)
                if (dist[i] == bv) loc = base + i;
            atomicMin(&s_far2[p], loc);
        }
        __syncthreads();
        far = s_far2[p];
    }
}

// ---------------- ball query -------------------------------------------------
__global__ void ballquery_kernel(const float* __restrict__ xyz,
                                 const float* __restrict__ newxyz) {
    int gw   = (blockIdx.x * blockDim.x + threadIdx.x) >> 5;
    int lane = threadIdx.x & 31;
    if (gw >= BATCH * SPTS) return;
    int b = gw >> 10;
    const float* X = xyz + (size_t)b * NPTS * 3;
    float cx = newxyz[gw*3 + 0];
    float cy = newxyz[gw*3 + 1];
    float cz = newxyz[gw*3 + 2];
    const float r2 = (float)(0.2 * 0.2);
    int cnt = 0, first = -1;
    int* out = g_gidx + (size_t)gw * KSAMP;
    for (int base = 0; base < NPTS && cnt < KSAMP; base += 32) {
        int p = base + lane;
        float dx = X[p*3+0] - cx, dy = X[p*3+1] - cy, dz = X[p*3+2] - cz;
        float d = dx*dx + dy*dy + dz*dz;
        bool in = (d <= r2);
        unsigned m = __ballot_sync(0xffffffffu, in);
        if (first < 0 && m) first = base + __ffs(m) - 1;
        int pos = cnt + __popc(m & ((1u << lane) - 1u));
        if (in && pos < KSAMP) out[pos] = p;
        cnt += __popc(m);
    }
    if (cnt < KSAMP) {
        int pos = cnt + lane;
        if (pos < KSAMP) out[pos] = first;
    }
}

// ---------------- persistent fused layer kernel (3xTF32 mma.sync) -----------
// 256 threads / 8 warps: warp = (M-slice = wid&3, N-half = wid>>2).
template <int L>
__global__ void __launch_bounds__(256, (L == 2) ? 2 : 3)
layer_kernel(const float* __restrict__ bias,
             const float* __restrict__ gprev,
             const float* __restrict__ beprev,
             const float* __restrict__ xyz,
             const float* __restrict__ newxyz) {
    constexpr int KIN   = (L == 0) ? 67 : 64;
    constexpr int KP    = (L == 0) ? 72 : 64;
    constexpr int NOUT  = (L == 2) ? 128 : 64;
    constexpr int XPs   = KP + 4;
    constexpr int WP2   = NOUT + 4;
    constexpr int NT    = 256;
    constexpr int NJ    = NOUT / 16;               // n-tiles per warp (4 or 8)
    constexpr int WOFF  = (L == 0) ? 0 : (L == 1) ? 72*64 : 72*64 + 64*64;
    constexpr int SOFF  = (L == 0) ? 0 : (L == 1) ? 128 : 256;
    constexpr int CSOFF = (L == 1) ? 0 : 128;
    constexpr int GRID  = (L == 2) ? (NSM * 2) : (NSM * 3);

    extern __shared__ __align__(16) float dynsmem[];
    float* Xs  = dynsmem;                          // [64][XPs]
    uint2* Ws2 = (uint2*)(dynsmem + 64 * XPs);     // [KP][WP2]

    __shared__ float    s_sc[64], s_sh[64];
    __shared__ float    s_sum[(L == 2) ? NOUT : 1];
    __shared__ float    s_sq[(L == 2) ? NOUT : 1];
    __shared__ unsigned s_max[(L == 2) ? 256 : 1];

    const int t = threadIdx.x;

    for (int i = t; i < KP * NOUT; i += NT) {
        int c = i / NOUT, o = i - c * NOUT;
        Ws2[c * WP2 + o] = g_wsplit[WOFF + i];
    }
    if (L > 0) {
        for (int i = t; i < 64; i += NT) {
            const float inv = 1.0f / (float)NROWS;
            float mean = g_stats[CSOFF + i] * inv;
            float var  = g_stats[CSOFF + 64 + i] * inv - mean * mean;
            float sc = gprev[i] * rsqrtf(var + 1e-5f);
            s_sc[i] = sc;
            s_sh[i] = beprev[i] - mean * sc;
        }
    }
    if (L == 2)
        for (int i = t; i < NOUT; i += NT) { s_sum[i] = 0.0f; s_sq[i] = 0.0f; }
    if (L == 0)
        for (int i = t; i < 64 * (KP - KIN); i += NT) {
            int r = i / (KP - KIN), c = i % (KP - KIN);
            Xs[r * XPs + KIN + c] = 0.0f;
        }

    const int lane = t & 31;
    const int wid  = t >> 5;
    const int g  = lane >> 2;
    const int tg = lane & 3;
    const int wr0 = (wid & 3) * 16;
    const int wo0 = (wid >> 2) * (NOUT / 2);

    float bb0[NJ], bb1[NJ];
    #pragma unroll
    for (int j = 0; j < NJ; j++) {
        int oc = wo0 + j * 8 + 2 * tg;
        bb0[j] = __ldg(&bias[oc]);
        bb1[j] = __ldg(&bias[oc + 1]);
    }
    float rsum[2 * NJ], rsq[2 * NJ];
    if (L < 2) {
        #pragma unroll
        for (int v = 0; v < 2 * NJ; v++) { rsum[v] = 0.0f; rsq[v] = 0.0f; }
    }

    // prefetch: 64 rows x 64 cols; 256 threads x 4 float4
    float4 pf[4];
    float  pxyz[3];
    const int pr = t >> 2;            // row 0..63
    const int c0 = (t & 3) * 16;      // col part

    auto prefetch = [&](int tile_) {
        if (L == 0) {
            int row = tile_ * 64 + pr;
            int pidx = g_gidx[row];
            int b = row >> 15;
            const float4* src = (const float4*)(g_ptsT +
                ((size_t)(b * NPTS + pidx)) * 64 + c0);
            #pragma unroll
            for (int q = 0; q < 4; q++) pf[q] = __ldg(src + q);
            if (t < 64) {
                int row2 = tile_ * 64 + t;
                int pidx2 = g_gidx[row2];
                int b2 = row2 >> 15, gg = row2 >> 5;
                #pragma unroll
                for (int d = 0; d < 3; d++)
                    pxyz[d] = __ldg(&xyz[((size_t)(b2 * NPTS + pidx2)) * 3 + d])
                            - __ldg(&newxyz[gg * 3 + d]);
            }
        } else {
            const float* prev = (L == 1) ? g_y1 : g_y2;
            const float4* src = (const float4*)(prev +
                (size_t)(tile_ * 64 + pr) * 64 + c0);
            #pragma unroll
            for (int q = 0; q < 4; q++) pf[q] = __ldg(src + q);
        }
    };

    prefetch(blockIdx.x);

    for (int tile = blockIdx.x; tile < NTILES; tile += GRID) {
        __syncthreads();
        if (L == 0) {
            float* xr = Xs + pr * XPs + c0;
            #pragma unroll
            for (int q = 0; q < 4; q++) ((float4*)xr)[q] = pf[q];
            if (t < 64) {
                Xs[t * XPs + 64] = pxyz[0];
                Xs[t * XPs + 65] = pxyz[1];
                Xs[t * XPs + 66] = pxyz[2];
            }
        } else {
            #pragma unroll
            for (int q = 0; q < 4; q++) {
                int c = c0 + 4 * q;
                float4 v = pf[q];
                float4 sc4 = *(const float4*)&s_sc[c];
                float4 sh4 = *(const float4*)&s_sh[c];
                v.x = fmaxf(fmaf(v.x, sc4.x, sh4.x), 0.0f);
                v.y = fmaxf(fmaf(v.y, sc4.y, sh4.y), 0.0f);
                v.z = fmaxf(fmaf(v.z, sc4.z, sh4.z), 0.0f);
                v.w = fmaxf(fmaf(v.w, sc4.w, sh4.w), 0.0f);
                *(float4*)&Xs[pr * XPs + c] = v;
            }
        }
        if (L == 2)
            for (int i = t; i < 256; i += NT) s_max[i] = 0u;
        __syncthreads();

        int next = tile + GRID;
        if (next < NTILES) prefetch(next);

        float acc[NJ][4];
        #pragma unroll
        for (int j = 0; j < NJ; j++)
            #pragma unroll
            for (int q = 0; q < 4; q++) acc[j][q] = 0.0f;

        #pragma unroll
        for (int ks = 0; ks < KP / 8; ks++) {
            const int k0 = ks * 8;
            uint32_t ah[4], al[4];
            {
                float a0 = Xs[(wr0 + g    ) * XPs + k0 + tg];
                float a1 = Xs[(wr0 + g + 8) * XPs + k0 + tg];
                float a2 = Xs[(wr0 + g    ) * XPs + k0 + tg + 4];
                float a3 = Xs[(wr0 + g + 8) * XPs + k0 + tg + 4];
                tf32_split(a0, ah[0], al[0]);
                tf32_split(a1, ah[1], al[1]);
                tf32_split(a2, ah[2], al[2]);
                tf32_split(a3, ah[3], al[3]);
            }
            const int bbase0 = (k0 + tg) * WP2 + wo0 + g;
            const int bbase1 = (k0 + tg + 4) * WP2 + wo0 + g;
            #pragma unroll
            for (int j = 0; j < NJ; j++) {
                uint2 b0 = Ws2[bbase0 + j * 8];
                uint2 b1 = Ws2[bbase1 + j * 8];
                mma16n8k8(acc[j], ah, b0.x, b1.x);   // hh
                mma16n8k8(acc[j], al, b0.x, b1.x);   // lh
                mma16n8k8(acc[j], ah, b0.y, b1.y);   // hl
            }
        }

        const int row0 = tile * 64;
        if (L < 2) {
            float* outy = (L == 0) ? g_y1 : g_y2;
            #pragma unroll
            for (int j = 0; j < NJ; j++) {
                int oc = wo0 + j * 8 + 2 * tg;
                float v00 = acc[j][0] + bb0[j], v01 = acc[j][1] + bb1[j];
                float v10 = acc[j][2] + bb0[j], v11 = acc[j][3] + bb1[j];
                rsum[2*j]   += v00 + v10;
                rsum[2*j+1] += v01 + v11;
                rsq[2*j]   = fmaf(v00, v00, rsq[2*j]);
                rsq[2*j]   = fmaf(v10, v10, rsq[2*j]);
                rsq[2*j+1] = fmaf(v01, v01, rsq[2*j+1]);
                rsq[2*j+1] = fmaf(v11, v11, rsq[2*j+1]);
                *(float2*)&outy[(size_t)(row0 + wr0 + g    ) * NOUT + oc] =
                    make_float2(v00, v01);
                *(float2*)&outy[(size_t)(row0 + wr0 + g + 8) * NOUT + oc] =
                    make_float2(v10, v11);
            }
        } else {
            const unsigned full = 0xffffffffu;
            #pragma unroll
            for (int j = 0; j < NJ; j++) {
                int oc = wo0 + j * 8 + 2 * tg;
                float v00 = acc[j][0] + bb0[j], v01 = acc[j][1] + bb1[j];
                float v10 = acc[j][2] + bb0[j], v11 = acc[j][3] + bb1[j];
                float s0 = v00 + v10, s1 = v01 + v11;
                float q0 = v00*v00 + v10*v10, q1 = v01*v01 + v11*v11;
                float m0 = fmaxf(v00, v10), m1 = fmaxf(v01, v11);
                #pragma unroll
                for (int off = 4; off < 32; off <<= 1) {
                    s0 += __shfl_xor_sync(full, s0, off);
                    s1 += __shfl_xor_sync(full, s1, off);
                    q0 += __shfl_xor_sync(full, q0, off);
                    q1 += __shfl_xor_sync(full, q1, off);
                    m0 = fmaxf(m0, __shfl_xor_sync(full, m0, off));
                    m1 = fmaxf(m1, __shfl_xor_sync(full, m1, off));
                }
                if (g == 0) {
                    atomicAdd(&s_sum[oc],     s0);
                    atomicAdd(&s_sum[oc + 1], s1);
                    atomicAdd(&s_sq[oc],      q0);
                    atomicAdd(&s_sq[oc + 1],  q1);
                    int grp = (wr0 >= 32);
                    atomicMax(&s_max[grp * 128 + oc],     enc_f(m0));
                    atomicMax(&s_max[grp * 128 + oc + 1], enc_f(m1));
                }
            }
            __syncthreads();
            for (int i = t; i < 256; i += NT) {
                int grp = i >> 7, o = i & 127;
                g_ymax[(size_t)(tile * 2 + grp) * 128 + o] = dec_f(s_max[i]);
            }
        }
    }

    if (L < 2) {
        const unsigned full = 0xffffffffu;
        #pragma unroll
        for (int v = 0; v < 2 * NJ; v++) {
            #pragma unroll
            for (int off = 4; off < 32; off <<= 1) {
                rsum[v] += __shfl_xor_sync(full, rsum[v], off);
                rsq[v]  += __shfl_xor_sync(full, rsq[v],  off);
            }
        }
        if (g == 0) {
            #pragma unroll
            for (int j = 0; j < NJ; j++) {
                int oc = wo0 + j * 8 + 2 * tg;
                atomicAdd(&g_stats[SOFF + oc],            rsum[2*j]);
                atomicAdd(&g_stats[SOFF + oc + 1],        rsum[2*j+1]);
                atomicAdd(&g_stats[SOFF + NOUT + oc],     rsq[2*j]);
                atomicAdd(&g_stats[SOFF + NOUT + oc + 1], rsq[2*j+1]);
            }
        }
    } else {
        __syncthreads();
        for (int i = t; i < NOUT; i += NT) {
            atomicAdd(&g_stats[SOFF + i],        s_sum[i]);
            atomicAdd(&g_stats[SOFF + NOUT + i], s_sq[i]);
        }
    }
}

// ---------------- finalize: bn+relu on maxima, transposed write -------------
__global__ void finalize_kernel(float* __restrict__ outp,
                                const float* __restrict__ g2,
                                const float* __restrict__ be2) {
    __shared__ float tile[32][129];
    int o0 = blockIdx.x * 32;
    int s0 = blockIdx.y * 128;
    int b  = blockIdx.z;
    int tx = threadIdx.x, ty = threadIdx.y;

    int o = o0 + tx;
    const float inv = 1.0f / (float)NROWS;
    float mean = g_stats[256 + o] * inv;
    float var  = g_stats[384 + o] * inv - mean * mean;
    float sc = g2[o] * rsqrtf(var + 1e-5f);
    float sh = be2[o] - mean * sc;

    for (int ss = ty; ss < 128; ss += 8) {
        float v = g_ymax[(size_t)(b * SPTS + s0 + ss) * 128 + o];
        tile[tx][ss] = fmaxf(fmaf(v, sc, sh), 0.0f);
    }
    __syncthreads();
    for (int oo = ty; oo < 32; oo += 8) {
        #pragma unroll
        for (int c = 0; c < 4; c++) {
            outp[((size_t)(b * 128 + o0 + oo)) * SPTS + s0 + c * 32 + tx] =
                tile[oo][c * 32 + tx];
        }
    }
}

// ---------------- launch ----------------------------------------------------
extern "C" void kernel_launch(void* const* d_in, const int* in_sizes, int n_in,
                              void* d_out, int out_size) {
    (void)in_sizes; (void)n_in; (void)out_size;
    const float* xyz = (const float*)d_in[0];
    const float* pts = (const float*)d_in[1];
    const float* w0 = (const float*)d_in[2];
    const float* b0 = (const float*)d_in[3];
    const float* g0 = (const float*)d_in[4];
    const float* be0 = (const float*)d_in[5];
    const float* w1 = (const float*)d_in[6];
    const float* b1 = (const float*)d_in[7];
    const float* g1 = (const float*)d_in[8];
    const float* be1 = (const float*)d_in[9];
    const float* w2 = (const float*)d_in[10];
    const float* b2 = (const float*)d_in[11];
    const float* g2 = (const float*)d_in[12];
    const float* be2 = (const float*)d_in[13];

    float* out = (float*)d_out;
    float* newxyz = out;                       // (B, SPTS, 3)
    float* outpts = out + OUT_XYZ_ELEMS;       // (B, 128, SPTS)

    const int L0_SMEM = (64 * 76) * 4 + (72 * 68) * 8;   // 58624
    const int L1_SMEM = (64 * 68) * 4 + (64 * 68) * 8;   // 52224
    const int L2_SMEM = (64 * 68) * 4 + (64 * 132) * 8;  // 84992
    cudaFuncSetAttribute(layer_kernel<0>,
                         cudaFuncAttributeMaxDynamicSharedMemorySize, L0_SMEM);
    cudaFuncSetAttribute(layer_kernel<1>,
                         cudaFuncAttributeMaxDynamicSharedMemorySize, L1_SMEM);
    cudaFuncSetAttribute(layer_kernel<2>,
                         cudaFuncAttributeMaxDynamicSharedMemorySize, L2_SMEM);

    // launches: transpose, fps, bq, layer0 (<- ncu 4th), layer1, layer2, finalize
    transpose_points_kernel<<<dim3(NPTS/32, CIN/32, BATCH), dim3(32, 8)>>>(
        pts, w0, w1, w2);
    fps_kernel<<<BATCH, 1024>>>(xyz, newxyz);
    ballquery_kernel<<<(BATCH * SPTS) / 8, 256>>>(xyz, newxyz);

    layer_kernel<0><<<NSM * 3, 256, L0_SMEM>>>(b0, nullptr, nullptr, xyz, newxyz);
    layer_kernel<1><<<NSM * 3, 256, L1_SMEM>>>(b1, g0, be0, xyz, newxyz);
    layer_kernel<2><<<NSM * 2, 256, L2_SMEM>>>(b2, g1, be1, xyz, newxyz);

    finalize_kernel<<<dim3(4, 8, BATCH), dim3(32, 8)>>>(outpts, g2, be2);
}

// round 15
// speedup vs baseline: 1.0312x; 1.0312x over previous
#include <cuda_runtime.h>
#include <cuda_bf16.h>
#include <math.h>
#include <stdint.h>

// Problem constants
#define BATCH   16
#define NPTS    8192
#define SPTS    1024        // NPOINT
#define KSAMP   32          // NSAMPLE
#define CIN     64          // input point feature channels
#define NROWS   (BATCH*SPTS*KSAMP)   // 524288
#define NGRP    (BATCH*SPTS)         // 16384
#define NTILES  (NROWS/64)           // 8192
#define OUT_XYZ_ELEMS (BATCH*SPTS*3) // 49152
#define NSM     148

typedef unsigned long long u64;

// ---------------- scratch (device globals; no dynamic alloc allowed) -------
__device__ float g_ptsT[(size_t)BATCH*NPTS*CIN];       // 33.5 MB  (B,N,C)
__device__ int   g_gidx[(size_t)BATCH*SPTS*KSAMP];     // ball query indices
__device__ float g_y1[(size_t)NROWS*64];               // 134 MB
__device__ float g_y2[(size_t)NROWS*64];               // 134 MB
__device__ float g_ymax[(size_t)NGRP*128];             // 8 MB (raw max over K)
__device__ float g_stats[512];                         // [L0 sum|sq][L1][L2]
// pre-split weights (tf32 hi/lo pairs), K-major [c][o]
__device__ uint2 g_wsplit[72*64 + 64*64 + 64*128];

// ---------------- helpers ---------------------------------------------------
__device__ __forceinline__ u64 pack2(float lo, float hi) {
    u64 r; asm("mov.b64 %0, {%1,%2};" : "=l"(r) : "f"(lo), "f"(hi)); return r;
}
__device__ __forceinline__ void unpack2(u64 v, float& lo, float& hi) {
    asm("mov.b64 {%0,%1}, %2;" : "=f"(lo), "=f"(hi) : "l"(v));
}
__device__ __forceinline__ u64 add2(u64 a, u64 b) {
    u64 r; asm("add.rn.f32x2 %0, %1, %2;" : "=l"(r) : "l"(a), "l"(b)); return r;
}
__device__ __forceinline__ u64 mul2(u64 a, u64 b) {
    u64 r; asm("mul.rn.f32x2 %0, %1, %2;" : "=l"(r) : "l"(a), "l"(b)); return r;
}
__device__ __forceinline__ u64 fma2(u64 a, u64 b, u64 c) {
    u64 r; asm("fma.rn.f32x2 %0, %1, %2, %3;" : "=l"(r) : "l"(a), "l"(b), "l"(c)); return r;
}
__device__ __forceinline__ unsigned redux_max_u32(unsigned v) {
    unsigned d; asm("redux.sync.max.u32 %0, %1, 0xffffffff;" : "=r"(d) : "r"(v));
    return d;
}
__device__ __forceinline__ unsigned enc_f(float f) {
    unsigned u = __float_as_uint(f);
    return (u & 0x80000000u) ? ~u : (u | 0x80000000u);
}
__device__ __forceinline__ float dec_f(unsigned u) {
    return __uint_as_float((u & 0x80000000u) ? (u & 0x7fffffffu) : ~u);
}
__device__ __forceinline__ void tf32_split(float v, uint32_t& hi, uint32_t& lo) {
    uint32_t h;
    asm("cvt.rna.tf32.f32 %0, %1;" : "=r"(h) : "f"(v));
    float r = v - __uint_as_float(h);
    asm("cvt.rna.tf32.f32 %0, %1;" : "=r"(lo) : "f"(r));
    hi = h;
}
__device__ __forceinline__ void mma16n8k8(float* c, const uint32_t* a,
                                          uint32_t b0, uint32_t b1) {
    asm volatile(
        "mma.sync.aligned.m16n8k8.row.col.f32.tf32.tf32.f32 "
        "{%0,%1,%2,%3}, {%4,%5,%6,%7}, {%8,%9}, {%0,%1,%2,%3};"
        : "+f"(c[0]), "+f"(c[1]), "+f"(c[2]), "+f"(c[3])
        : "r"(a[0]), "r"(a[1]), "r"(a[2]), "r"(a[3]), "r"(b0), "r"(b1));
}

// ---------------- fused FPS (blocks 0..15) + transpose/wsplit (blocks 16+) --
// FPS path: byte-equivalent to the measured-best R9 kernel (460us): 512 thr,
// 16 pts/thread in registers, two barriers/iter, redux warp max -> smem ->
// redux over 16 -> candidate equality scan + atomicMin (first-occurrence
// argmax == jnp.argmax). Transpose/wsplit/stats blocks run on the other 132
// SMs, fully hidden under FPS (static smem only, ~8.5KB).
__global__ void __launch_bounds__(512)
fps_fused_kernel(const float* __restrict__ xyz,
                 const float* __restrict__ pts,
                 const float* __restrict__ w0,
                 const float* __restrict__ w1,
                 const float* __restrict__ w2,
                 float* __restrict__ out_newxyz) {
    __shared__ float    s_tile[2][32][33];   // transpose duty
    __shared__ unsigned s_val[16];           // FPS duty
    __shared__ int      s_far2[2];

    const int t = threadIdx.x;

    if (blockIdx.x >= BATCH) {
        // ---------- transpose / wsplit / stats duty ----------
        int e = blockIdx.x - BATCH;          // 0..4095
        if (e == 0) g_stats[t] = 0.0f;       // t covers all 512
        if (e < 3) {                          // W pre-split for layer e
            int L = e;
            int KIN  = (L == 0) ? 67 : 64;
            int KP   = (L == 0) ? 72 : 64;
            int NOUT = (L == 2) ? 128 : 64;
            int OFF  = (L == 0) ? 0 : (L == 1) ? 72*64 : 72*64 + 64*64;
            const float* W = (L == 0) ? w0 : (L == 1) ? w1 : w2;
            for (int i = t; i < KP * NOUT; i += 512) {
                int c = i / NOUT, o = i - c * NOUT;
                float v = (c < KIN) ? W[o * KIN + c] : 0.0f;
                uint32_t hi, lo;
                tf32_split(v, hi, lo);
                g_wsplit[OFF + i] = make_uint2(hi, lo);
            }
        }
        // two 32x32 transpose tiles per block
        int half = t >> 8;                   // 0/1
        int tid2 = t & 255;
        int tx = tid2 & 31, ty = tid2 >> 5;  // 32 x 8
        int tt = e * 2 + half;               // tile id 0..8191
        int n0 = (tt & 255) * 32;
        int c0 = ((tt >> 8) & 1) * 32;
        int b  = tt >> 9;
        #pragma unroll
        for (int i = 0; i < 32; i += 8)
            s_tile[half][ty + i][tx] =
                pts[((size_t)b * CIN + c0 + ty + i) * NPTS + n0 + tx];
        __syncthreads();
        #pragma unroll
        for (int i = 0; i < 32; i += 8)
            g_ptsT[((size_t)b * NPTS + n0 + ty + i) * CIN + c0 + tx] =
                s_tile[half][tx][ty + i];
        return;
    }

    // ---------- FPS (R9 exact) ----------
    const int b = blockIdx.x;
    const float* X = xyz + (size_t)b * NPTS * 3;
    const int base = t * 16;

    u64 px2[8], py2[8], pz2[8];
    float dist[16];
    #pragma unroll
    for (int i = 0; i < 8; i++) {
        int p = base + 2 * i;
        float x0 = X[p*3+0], y0 = X[p*3+1], z0 = X[p*3+2];
        float x1 = X[p*3+3], y1 = X[p*3+4], z1 = X[p*3+5];
        px2[i] = pack2(x0, x1);
        py2[i] = pack2(y0, y1);
        pz2[i] = pack2(z0, z1);
        dist[2*i] = 1e10f; dist[2*i+1] = 1e10f;
    }

    int far = 0;
    for (int it = 0; it < SPTS; it++) {
        float cx = X[far*3 + 0];
        float cy = X[far*3 + 1];
        float cz = X[far*3 + 2];
        const int p = it & 1;
        if (t == 0) {
            float* o = out_newxyz + ((size_t)b*SPTS + it) * 3;
            o[0] = cx; o[1] = cy; o[2] = cz;
            s_far2[p] = 0x7fffffff;
        }
        u64 ncx2 = pack2(-cx, -cx);
        u64 ncy2 = pack2(-cy, -cy);
        u64 ncz2 = pack2(-cz, -cz);

        float best = 0.0f;
        #pragma unroll
        for (int i = 0; i < 8; i++) {
            u64 dx2 = add2(px2[i], ncx2);
            u64 dy2 = add2(py2[i], ncy2);
            u64 dz2 = add2(pz2[i], ncz2);
            u64 d2 = mul2(dx2, dx2);
            d2 = fma2(dy2, dy2, d2);
            d2 = fma2(dz2, dz2, d2);
            float d0, d1; unpack2(d2, d0, d1);
            float n0 = fminf(dist[2*i],   d0); dist[2*i]   = n0;
            float n1 = fminf(dist[2*i+1], d1); dist[2*i+1] = n1;
            best = fmaxf(best, fmaxf(n0, n1));
        }

        unsigned bb = __float_as_uint(best);
        unsigned wmax = redux_max_u32(bb);
        if ((t & 31) == 0) s_val[t >> 5] = wmax;
        __syncthreads();

        unsigned gmax = redux_max_u32(s_val[t & 15]);

        if (bb == gmax) {
            float bv = __uint_as_float(gmax);
            int loc = 0x7fffffff;
            #pragma unroll
            for (int i = 15; i >= 0; --i)
                if (dist[i] == bv) loc = base + i;
            atomicMin(&s_far2[p], loc);
        }
        __syncthreads();
        far = s_far2[p];
    }
}

// ---------------- ball query -------------------------------------------------
__global__ void ballquery_kernel(const float* __restrict__ xyz,
                                 const float* __restrict__ newxyz) {
    int gw   = (blockIdx.x * blockDim.x + threadIdx.x) >> 5;
    int lane = threadIdx.x & 31;
    if (gw >= BATCH * SPTS) return;
    int b = gw >> 10;
    const float* X = xyz + (size_t)b * NPTS * 3;
    float cx = newxyz[gw*3 + 0];
    float cy = newxyz[gw*3 + 1];
    float cz = newxyz[gw*3 + 2];
    const float r2 = (float)(0.2 * 0.2);
    int cnt = 0, first = -1;
    int* out = g_gidx + (size_t)gw * KSAMP;
    for (int base = 0; base < NPTS && cnt < KSAMP; base += 32) {
        int p = base + lane;
        float dx = X[p*3+0] - cx, dy = X[p*3+1] - cy, dz = X[p*3+2] - cz;
        float d = dx*dx + dy*dy + dz*dz;
        bool in = (d <= r2);
        unsigned m = __ballot_sync(0xffffffffu, in);
        if (first < 0 && m) first = base + __ffs(m) - 1;
        int pos = cnt + __popc(m & ((1u << lane) - 1u));
        if (in && pos < KSAMP) out[pos] = p;
        cnt += __popc(m);
    }
    if (cnt < KSAMP) {
        int pos = cnt + lane;
        if (pos < KSAMP) out[pos] = first;
    }
}

// ---------------- persistent fused layer kernel (3xTF32 mma.sync) -----------
// 256 threads / 8 warps: warp = (M-slice = wid&3, N-half = wid>>2).
template <int L>
__global__ void __launch_bounds__(256, (L == 2) ? 2 : 3)
layer_kernel(const float* __restrict__ bias,
             const float* __restrict__ gprev,
             const float* __restrict__ beprev,
             const float* __restrict__ xyz,
             const float* __restrict__ newxyz) {
    constexpr int KIN   = (L == 0) ? 67 : 64;
    constexpr int KP    = (L == 0) ? 72 : 64;
    constexpr int NOUT  = (L == 2) ? 128 : 64;
    constexpr int XPs   = KP + 4;
    constexpr int WP2   = NOUT + 4;
    constexpr int NT    = 256;
    constexpr int NJ    = NOUT / 16;               // n-tiles per warp (4 or 8)
    constexpr int WOFF  = (L == 0) ? 0 : (L == 1) ? 72*64 : 72*64 + 64*64;
    constexpr int SOFF  = (L == 0) ? 0 : (L == 1) ? 128 : 256;
    constexpr int CSOFF = (L == 1) ? 0 : 128;
    constexpr int GRID  = (L == 2) ? (NSM * 2) : (NSM * 3);

    extern __shared__ __align__(16) float dynsmem[];
    float* Xs  = dynsmem;                          // [64][XPs]
    uint2* Ws2 = (uint2*)(dynsmem + 64 * XPs);     // [KP][WP2]

    __shared__ float    s_sc[64], s_sh[64];
    __shared__ float    s_sum[(L == 2) ? NOUT : 1];
    __shared__ float    s_sq[(L == 2) ? NOUT : 1];
    __shared__ unsigned s_max[(L == 2) ? 256 : 1];

    const int t = threadIdx.x;

    for (int i = t; i < KP * NOUT; i += NT) {
        int c = i / NOUT, o = i - c * NOUT;
        Ws2[c * WP2 + o] = g_wsplit[WOFF + i];
    }
    if (L > 0) {
        for (int i = t; i < 64; i += NT) {
            const float inv = 1.0f / (float)NROWS;
            float mean = g_stats[CSOFF + i] * inv;
            float var  = g_stats[CSOFF + 64 + i] * inv - mean * mean;
            float sc = gprev[i] * rsqrtf(var + 1e-5f);
            s_sc[i] = sc;
            s_sh[i] = beprev[i] - mean * sc;
        }
    }
    if (L == 2)
        for (int i = t; i < NOUT; i += NT) { s_sum[i] = 0.0f; s_sq[i] = 0.0f; }
    if (L == 0)
        for (int i = t; i < 64 * (KP - KIN); i += NT) {
            int r = i / (KP - KIN), c = i % (KP - KIN);
            Xs[r * XPs + KIN + c] = 0.0f;
        }

    const int lane = t & 31;
    const int wid  = t >> 5;
    const int g  = lane >> 2;
    const int tg = lane & 3;
    const int wr0 = (wid & 3) * 16;
    const int wo0 = (wid >> 2) * (NOUT / 2);

    float bb0[NJ], bb1[NJ];
    #pragma unroll
    for (int j = 0; j < NJ; j++) {
        int oc = wo0 + j * 8 + 2 * tg;
        bb0[j] = __ldg(&bias[oc]);
        bb1[j] = __ldg(&bias[oc + 1]);
    }
    float rsum[2 * NJ], rsq[2 * NJ];
    if (L < 2) {
        #pragma unroll
        for (int v = 0; v < 2 * NJ; v++) { rsum[v] = 0.0f; rsq[v] = 0.0f; }
    }

    // prefetch: 64 rows x 64 cols; 256 threads x 4 float4
    float4 pf[4];
    float  pxyz[3];
    const int pr = t >> 2;            // row 0..63
    const int c0 = (t & 3) * 16;      // col part

    auto prefetch = [&](int tile_) {
        if (L == 0) {
            int row = tile_ * 64 + pr;
            int pidx = g_gidx[row];
            int b = row >> 15;
            const float4* src = (const float4*)(g_ptsT +
                ((size_t)(b * NPTS + pidx)) * 64 + c0);
            #pragma unroll
            for (int q = 0; q < 4; q++) pf[q] = __ldg(src + q);
            if (t < 64) {
                int row2 = tile_ * 64 + t;
                int pidx2 = g_gidx[row2];
                int b2 = row2 >> 15, gg = row2 >> 5;
                #pragma unroll
                for (int d = 0; d < 3; d++)
                    pxyz[d] = __ldg(&xyz[((size_t)(b2 * NPTS + pidx2)) * 3 + d])
                            - __ldg(&newxyz[gg * 3 + d]);
            }
        } else {
            const float* prev = (L == 1) ? g_y1 : g_y2;
            const float4* src = (const float4*)(prev +
                (size_t)(tile_ * 64 + pr) * 64 + c0);
            #pragma unroll
            for (int q = 0; q < 4; q++) pf[q] = __ldg(src + q);
        }
    };

    prefetch(blockIdx.x);

    for (int tile = blockIdx.x; tile < NTILES; tile += GRID) {
        __syncthreads();
        if (L == 0) {
            float* xr = Xs + pr * XPs + c0;
            #pragma unroll
            for (int q = 0; q < 4; q++) ((float4*)xr)[q] = pf[q];
            if (t < 64) {
                Xs[t * XPs + 64] = pxyz[0];
                Xs[t * XPs + 65] = pxyz[1];
                Xs[t * XPs + 66] = pxyz[2];
            }
        } else {
            #pragma unroll
            for (int q = 0; q < 4; q++) {
                int c = c0 + 4 * q;
                float4 v = pf[q];
                float4 sc4 = *(const float4*)&s_sc[c];
                float4 sh4 = *(const float4*)&s_sh[c];
                v.x = fmaxf(fmaf(v.x, sc4.x, sh4.x), 0.0f);
                v.y = fmaxf(fmaf(v.y, sc4.y, sh4.y), 0.0f);
                v.z = fmaxf(fmaf(v.z, sc4.z, sh4.z), 0.0f);
                v.w = fmaxf(fmaf(v.w, sc4.w, sh4.w), 0.0f);
                *(float4*)&Xs[pr * XPs + c] = v;
            }
        }
        if (L == 2)
            for (int i = t; i < 256; i += NT) s_max[i] = 0u;
        __syncthreads();

        int next = tile + GRID;
        if (next < NTILES) prefetch(next);

        float acc[NJ][4];
        #pragma unroll
        for (int j = 0; j < NJ; j++)
            #pragma unroll
            for (int q = 0; q < 4; q++) acc[j][q] = 0.0f;

        #pragma unroll
        for (int ks = 0; ks < KP / 8; ks++) {
            const int k0 = ks * 8;
            uint32_t ah[4], al[4];
            {
                float a0 = Xs[(wr0 + g    ) * XPs + k0 + tg];
                float a1 = Xs[(wr0 + g + 8) * XPs + k0 + tg];
                float a2 = Xs[(wr0 + g    ) * XPs + k0 + tg + 4];
                float a3 = Xs[(wr0 + g + 8) * XPs + k0 + tg + 4];
                tf32_split(a0, ah[0], al[0]);
                tf32_split(a1, ah[1], al[1]);
                tf32_split(a2, ah[2], al[2]);
                tf32_split(a3, ah[3], al[3]);
            }
            const int bbase0 = (k0 + tg) * WP2 + wo0 + g;
            const int bbase1 = (k0 + tg + 4) * WP2 + wo0 + g;
            #pragma unroll
            for (int j = 0; j < NJ; j++) {
                uint2 b0 = Ws2[bbase0 + j * 8];
                uint2 b1 = Ws2[bbase1 + j * 8];
                mma16n8k8(acc[j], ah, b0.x, b1.x);   // hh
                mma16n8k8(acc[j], al, b0.x, b1.x);   // lh
                mma16n8k8(acc[j], ah, b0.y, b1.y);   // hl
            }
        }

        const int row0 = tile * 64;
        if (L < 2) {
            float* outy = (L == 0) ? g_y1 : g_y2;
            #pragma unroll
            for (int j = 0; j < NJ; j++) {
                int oc = wo0 + j * 8 + 2 * tg;
                float v00 = acc[j][0] + bb0[j], v01 = acc[j][1] + bb1[j];
                float v10 = acc[j][2] + bb0[j], v11 = acc[j][3] + bb1[j];
                rsum[2*j]   += v00 + v10;
                rsum[2*j+1] += v01 + v11;
                rsq[2*j]   = fmaf(v00, v00, rsq[2*j]);
                rsq[2*j]   = fmaf(v10, v10, rsq[2*j]);
                rsq[2*j+1] = fmaf(v01, v01, rsq[2*j+1]);
                rsq[2*j+1] = fmaf(v11, v11, rsq[2*j+1]);
                *(float2*)&outy[(size_t)(row0 + wr0 + g    ) * NOUT + oc] =
                    make_float2(v00, v01);
                *(float2*)&outy[(size_t)(row0 + wr0 + g + 8) * NOUT + oc] =
                    make_float2(v10, v11);
            }
        } else {
            const unsigned full = 0xffffffffu;
            #pragma unroll
            for (int j = 0; j < NJ; j++) {
                int oc = wo0 + j * 8 + 2 * tg;
                float v00 = acc[j][0] + bb0[j], v01 = acc[j][1] + bb1[j];
                float v10 = acc[j][2] + bb0[j], v11 = acc[j][3] + bb1[j];
                float s0 = v00 + v10, s1 = v01 + v11;
                float q0 = v00*v00 + v10*v10, q1 = v01*v01 + v11*v11;
                float m0 = fmaxf(v00, v10), m1 = fmaxf(v01, v11);
                #pragma unroll
                for (int off = 4; off < 32; off <<= 1) {
                    s0 += __shfl_xor_sync(full, s0, off);
                    s1 += __shfl_xor_sync(full, s1, off);
                    q0 += __shfl_xor_sync(full, q0, off);
                    q1 += __shfl_xor_sync(full, q1, off);
                    m0 = fmaxf(m0, __shfl_xor_sync(full, m0, off));
                    m1 = fmaxf(m1, __shfl_xor_sync(full, m1, off));
                }
                if (g == 0) {
                    atomicAdd(&s_sum[oc],     s0);
                    atomicAdd(&s_sum[oc + 1], s1);
                    atomicAdd(&s_sq[oc],      q0);
                    atomicAdd(&s_sq[oc + 1],  q1);
                    int grp = (wr0 >= 32);
                    atomicMax(&s_max[grp * 128 + oc],     enc_f(m0));
                    atomicMax(&s_max[grp * 128 + oc + 1], enc_f(m1));
                }
            }
            __syncthreads();
            for (int i = t; i < 256; i += NT) {
                int grp = i >> 7, o = i & 127;
                g_ymax[(size_t)(tile * 2 + grp) * 128 + o] = dec_f(s_max[i]);
            }
        }
    }

    if (L < 2) {
        const unsigned full = 0xffffffffu;
        #pragma unroll
        for (int v = 0; v < 2 * NJ; v++) {
            #pragma unroll
            for (int off = 4; off < 32; off <<= 1) {
                rsum[v] += __shfl_xor_sync(full, rsum[v], off);
                rsq[v]  += __shfl_xor_sync(full, rsq[v],  off);
            }
        }
        if (g == 0) {
            #pragma unroll
            for (int j = 0; j < NJ; j++) {
                int oc = wo0 + j * 8 + 2 * tg;
                atomicAdd(&g_stats[SOFF + oc],            rsum[2*j]);
                atomicAdd(&g_stats[SOFF + oc + 1],        rsum[2*j+1]);
                atomicAdd(&g_stats[SOFF + NOUT + oc],     rsq[2*j]);
                atomicAdd(&g_stats[SOFF + NOUT + oc + 1], rsq[2*j+1]);
            }
        }
    } else {
        __syncthreads();
        for (int i = t; i < NOUT; i += NT) {
            atomicAdd(&g_stats[SOFF + i],        s_sum[i]);
            atomicAdd(&g_stats[SOFF + NOUT + i], s_sq[i]);
        }
    }
}

// ---------------- finalize: bn+relu on maxima, transposed write -------------
__global__ void finalize_kernel(float* __restrict__ outp,
                                const float* __restrict__ g2,
                                const float* __restrict__ be2) {
    __shared__ float tile[32][129];
    int o0 = blockIdx.x * 32;
    int s0 = blockIdx.y * 128;
    int b  = blockIdx.z;
    int tx = threadIdx.x, ty = threadIdx.y;

    int o = o0 + tx;
    const float inv = 1.0f / (float)NROWS;
    float mean = g_stats[256 + o] * inv;
    float var  = g_stats[384 + o] * inv - mean * mean;
    float sc = g2[o] * rsqrtf(var + 1e-5f);
    float sh = be2[o] - mean * sc;

    for (int ss = ty; ss < 128; ss += 8) {
        float v = g_ymax[(size_t)(b * SPTS + s0 + ss) * 128 + o];
        tile[tx][ss] = fmaxf(fmaf(v, sc, sh), 0.0f);
    }
    __syncthreads();
    for (int oo = ty; oo < 32; oo += 8) {
        #pragma unroll
        for (int c = 0; c < 4; c++) {
            outp[((size_t)(b * 128 + o0 + oo)) * SPTS + s0 + c * 32 + tx] =
                tile[oo][c * 32 + tx];
        }
    }
}

// ---------------- launch ----------------------------------------------------
extern "C" void kernel_launch(void* const* d_in, const int* in_sizes, int n_in,
                              void* d_out, int out_size) {
    (void)in_sizes; (void)n_in; (void)out_size;
    const float* xyz = (const float*)d_in[0];
    const float* pts = (const float*)d_in[1];
    const float* w0 = (const float*)d_in[2];
    const float* b0 = (const float*)d_in[3];
    const float* g0 = (const float*)d_in[4];
    const float* be0 = (const float*)d_in[5];
    const float* w1 = (const float*)d_in[6];
    const float* b1 = (const float*)d_in[7];
    const float* g1 = (const float*)d_in[8];
    const float* be1 = (const float*)d_in[9];
    const float* w2 = (const float*)d_in[10];
    const float* b2 = (const float*)d_in[11];
    const float* g2 = (const float*)d_in[12];
    const float* be2 = (const float*)d_in[13];

    float* out = (float*)d_out;
    float* newxyz = out;                       // (B, SPTS, 3)
    float* outpts = out + OUT_XYZ_ELEMS;       // (B, 128, SPTS)

    const int L0_SMEM = (64 * 76) * 4 + (72 * 68) * 8;   // 58624
    const int L1_SMEM = (64 * 68) * 4 + (64 * 68) * 8;   // 52224
    const int L2_SMEM = (64 * 68) * 4 + (64 * 132) * 8;  // 84992
    cudaFuncSetAttribute(layer_kernel<0>,
                         cudaFuncAttributeMaxDynamicSharedMemorySize, L0_SMEM);
    cudaFuncSetAttribute(layer_kernel<1>,
                         cudaFuncAttributeMaxDynamicSharedMemorySize, L1_SMEM);
    cudaFuncSetAttribute(layer_kernel<2>,
                         cudaFuncAttributeMaxDynamicSharedMemorySize, L2_SMEM);

    // launches: fused, bq, layer0, layer1 (<- ncu 4th), layer2, finalize
    fps_fused_kernel<<<BATCH + NTILES / 2, 512>>>(xyz, pts, w0, w1, w2, newxyz);
    ballquery_kernel<<<(BATCH * SPTS) / 8, 256>>>(xyz, newxyz);

    layer_kernel<0><<<NSM * 3, 256, L0_SMEM>>>(b0, nullptr, nullptr, xyz, newxyz);
    layer_kernel<1><<<NSM * 3, 256, L1_SMEM>>>(b1, g0, be0, xyz, newxyz);
    layer_kernel<2><<<NSM * 2, 256, L2_SMEM>>>(b2, g1, be1, xyz, newxyz);

    finalize_kernel<<<dim3(4, 8, BATCH), dim3(32, 8)>>>(outpts, g2, be2);
}

// round 17
// speedup vs baseline: 1.0483x; 1.0166x over previous
#include <cuda_runtime.h>
#include <cuda_bf16.h>
#include <math.h>
#include <stdint.h>

// Problem constants
#define BATCH   16
#define NPTS    8192
#define SPTS    1024        // NPOINT
#define KSAMP   32          // NSAMPLE
#define CIN     64          // input point feature channels
#define NROWS   (BATCH*SPTS*KSAMP)   // 524288
#define NGRP    (BATCH*SPTS)         // 16384
#define NTILES  (NROWS/64)           // 8192
#define OUT_XYZ_ELEMS (BATCH*SPTS*3) // 49152
#define NSM     148

typedef unsigned long long u64;

// ---------------- scratch (device globals; no dynamic alloc allowed) -------
__device__ float g_ptsT[(size_t)BATCH*NPTS*CIN];       // 33.5 MB  (B,N,C)
__device__ int   g_gidx[(size_t)BATCH*SPTS*KSAMP];     // ball query indices
__device__ float g_y1[(size_t)NROWS*64];               // 134 MB
__device__ float g_y2[(size_t)NROWS*64];               // 134 MB
__device__ float g_ymax[(size_t)NGRP*128];             // 8 MB (raw max over K)
__device__ float g_stats[512];                         // [L0 sum|sq][L1][L2]
// pre-split weights (tf32 hi/lo pairs), K-major [c][o]
__device__ uint2 g_wsplit[72*64 + 64*64 + 64*128];

// ---------------- helpers ---------------------------------------------------
__device__ __forceinline__ u64 pack2(float lo, float hi) {
    u64 r; asm("mov.b64 %0, {%1,%2};" : "=l"(r) : "f"(lo), "f"(hi)); return r;
}
__device__ __forceinline__ void unpack2(u64 v, float& lo, float& hi) {
    asm("mov.b64 {%0,%1}, %2;" : "=f"(lo), "=f"(hi) : "l"(v));
}
__device__ __forceinline__ u64 add2(u64 a, u64 b) {
    u64 r; asm("add.rn.f32x2 %0, %1, %2;" : "=l"(r) : "l"(a), "l"(b)); return r;
}
__device__ __forceinline__ u64 mul2(u64 a, u64 b) {
    u64 r; asm("mul.rn.f32x2 %0, %1, %2;" : "=l"(r) : "l"(a), "l"(b)); return r;
}
__device__ __forceinline__ u64 fma2(u64 a, u64 b, u64 c) {
    u64 r; asm("fma.rn.f32x2 %0, %1, %2, %3;" : "=l"(r) : "l"(a), "l"(b), "l"(c)); return r;
}
__device__ __forceinline__ unsigned redux_max_u32(unsigned v) {
    unsigned d; asm("redux.sync.max.u32 %0, %1, 0xffffffff;" : "=r"(d) : "r"(v));
    return d;
}
__device__ __forceinline__ unsigned enc_f(float f) {
    unsigned u = __float_as_uint(f);
    return (u & 0x80000000u) ? ~u : (u | 0x80000000u);
}
__device__ __forceinline__ float dec_f(unsigned u) {
    return __uint_as_float((u & 0x80000000u) ? (u & 0x7fffffffu) : ~u);
}
__device__ __forceinline__ void tf32_split(float v, uint32_t& hi, uint32_t& lo) {
    uint32_t h;
    asm("cvt.rna.tf32.f32 %0, %1;" : "=r"(h) : "f"(v));
    float r = v - __uint_as_float(h);
    asm("cvt.rna.tf32.f32 %0, %1;" : "=r"(lo) : "f"(r));
    hi = h;
}
__device__ __forceinline__ void mma16n8k8(float* c, const uint32_t* a,
                                          uint32_t b0, uint32_t b1) {
    asm volatile(
        "mma.sync.aligned.m16n8k8.row.col.f32.tf32.tf32.f32 "
        "{%0,%1,%2,%3}, {%4,%5,%6,%7}, {%8,%9}, {%0,%1,%2,%3};"
        : "+f"(c[0]), "+f"(c[1]), "+f"(c[2]), "+f"(c[3])
        : "r"(a[0]), "r"(a[1]), "r"(a[2]), "r"(a[3]), "r"(b0), "r"(b1));
}

// ---------------- fused FPS (blocks 0..15) + transpose/wsplit (blocks 16+) --
// FPS path: R15-exact (measured best): 512 thr, 16 pts/thread, f32x2 distance
// math with scalar fminf/fmaxf tail, two barriers/iter, redux warp max ->
// smem -> redux over 16 -> candidate equality scan + atomicMin
// (first-occurrence argmax == jnp.argmax). Transpose/wsplit/stats blocks run
// on the other 132 SMs, hidden under FPS.
__global__ void __launch_bounds__(512)
fps_fused_kernel(const float* __restrict__ xyz,
                 const float* __restrict__ pts,
                 const float* __restrict__ w0,
                 const float* __restrict__ w1,
                 const float* __restrict__ w2,
                 float* __restrict__ out_newxyz) {
    __shared__ float    s_tile[2][32][33];   // transpose duty
    __shared__ unsigned s_val[16];           // FPS duty
    __shared__ int      s_far2[2];

    const int t = threadIdx.x;

    if (blockIdx.x >= BATCH) {
        // ---------- transpose / wsplit / stats duty ----------
        int e = blockIdx.x - BATCH;          // 0..4095
        if (e == 0) g_stats[t] = 0.0f;       // t covers all 512
        if (e < 3) {                          // W pre-split for layer e
            int L = e;
            int KIN  = (L == 0) ? 67 : 64;
            int KP   = (L == 0) ? 72 : 64;
            int NOUT = (L == 2) ? 128 : 64;
            int OFF  = (L == 0) ? 0 : (L == 1) ? 72*64 : 72*64 + 64*64;
            const float* W = (L == 0) ? w0 : (L == 1) ? w1 : w2;
            for (int i = t; i < KP * NOUT; i += 512) {
                int c = i / NOUT, o = i - c * NOUT;
                float v = (c < KIN) ? W[o * KIN + c] : 0.0f;
                uint32_t hi, lo;
                tf32_split(v, hi, lo);
                g_wsplit[OFF + i] = make_uint2(hi, lo);
            }
        }
        // two 32x32 transpose tiles per block
        int half = t >> 8;                   // 0/1
        int tid2 = t & 255;
        int tx = tid2 & 31, ty = tid2 >> 5;  // 32 x 8
        int tt = e * 2 + half;               // tile id 0..8191
        int n0 = (tt & 255) * 32;
        int c0 = ((tt >> 8) & 1) * 32;
        int b  = tt >> 9;
        #pragma unroll
        for (int i = 0; i < 32; i += 8)
            s_tile[half][ty + i][tx] =
                pts[((size_t)b * CIN + c0 + ty + i) * NPTS + n0 + tx];
        __syncthreads();
        #pragma unroll
        for (int i = 0; i < 32; i += 8)
            g_ptsT[((size_t)b * NPTS + n0 + ty + i) * CIN + c0 + tx] =
                s_tile[half][tx][ty + i];
        return;
    }

    // ---------- FPS (R15 exact) ----------
    const int b = blockIdx.x;
    const float* X = xyz + (size_t)b * NPTS * 3;
    const int base = t * 16;

    u64 px2[8], py2[8], pz2[8];
    float dist[16];
    #pragma unroll
    for (int i = 0; i < 8; i++) {
        int p = base + 2 * i;
        float x0 = X[p*3+0], y0 = X[p*3+1], z0 = X[p*3+2];
        float x1 = X[p*3+3], y1 = X[p*3+4], z1 = X[p*3+5];
        px2[i] = pack2(x0, x1);
        py2[i] = pack2(y0, y1);
        pz2[i] = pack2(z0, z1);
        dist[2*i] = 1e10f; dist[2*i+1] = 1e10f;
    }

    int far = 0;
    for (int it = 0; it < SPTS; it++) {
        float cx = X[far*3 + 0];
        float cy = X[far*3 + 1];
        float cz = X[far*3 + 2];
        const int p = it & 1;
        if (t == 0) {
            float* o = out_newxyz + ((size_t)b*SPTS + it) * 3;
            o[0] = cx; o[1] = cy; o[2] = cz;
            s_far2[p] = 0x7fffffff;
        }
        u64 ncx2 = pack2(-cx, -cx);
        u64 ncy2 = pack2(-cy, -cy);
        u64 ncz2 = pack2(-cz, -cz);

        float best = 0.0f;
        #pragma unroll
        for (int i = 0; i < 8; i++) {
            u64 dx2 = add2(px2[i], ncx2);
            u64 dy2 = add2(py2[i], ncy2);
            u64 dz2 = add2(pz2[i], ncz2);
            u64 d2 = mul2(dx2, dx2);
            d2 = fma2(dy2, dy2, d2);
            d2 = fma2(dz2, dz2, d2);
            float d0, d1; unpack2(d2, d0, d1);
            float n0 = fminf(dist[2*i],   d0); dist[2*i]   = n0;
            float n1 = fminf(dist[2*i+1], d1); dist[2*i+1] = n1;
            best = fmaxf(best, fmaxf(n0, n1));
        }

        unsigned bb = __float_as_uint(best);
        unsigned wmax = redux_max_u32(bb);
        if ((t & 31) == 0) s_val[t >> 5] = wmax;
        __syncthreads();

        unsigned gmax = redux_max_u32(s_val[t & 15]);

        if (bb == gmax) {
            float bv = __uint_as_float(gmax);
            int loc = 0x7fffffff;
            #pragma unroll
            for (int i = 15; i >= 0; --i)
                if (dist[i] == bv) loc = base + i;
            atomicMin(&s_far2[p], loc);
        }
        __syncthreads();
        far = s_far2[p];
    }
}

// ---------------- ball query -------------------------------------------------
__global__ void ballquery_kernel(const float* __restrict__ xyz,
                                 const float* __restrict__ newxyz) {
    int gw   = (blockIdx.x * blockDim.x + threadIdx.x) >> 5;
    int lane = threadIdx.x & 31;
    if (gw >= BATCH * SPTS) return;
    int b = gw >> 10;
    const float* X = xyz + (size_t)b * NPTS * 3;
    float cx = newxyz[gw*3 + 0];
    float cy = newxyz[gw*3 + 1];
    float cz = newxyz[gw*3 + 2];
    const float r2 = (float)(0.2 * 0.2);
    int cnt = 0, first = -1;
    int* out = g_gidx + (size_t)gw * KSAMP;
    for (int base = 0; base < NPTS && cnt < KSAMP; base += 32) {
        int p = base + lane;
        float dx = X[p*3+0] - cx, dy = X[p*3+1] - cy, dz = X[p*3+2] - cz;
        float d = dx*dx + dy*dy + dz*dz;
        bool in = (d <= r2);
        unsigned m = __ballot_sync(0xffffffffu, in);
        if (first < 0 && m) first = base + __ffs(m) - 1;
        int pos = cnt + __popc(m & ((1u << lane) - 1u));
        if (in && pos < KSAMP) out[pos] = p;
        cnt += __popc(m);
    }
    if (cnt < KSAMP) {
        int pos = cnt + lane;
        if (pos < KSAMP) out[pos] = first;
    }
}

// ---------------- persistent fused layer kernel (3xTF32 mma.sync) -----------
// 256 threads / 8 warps: warp = (M-slice = wid&3, N-half = wid>>2).
// ALL layers now carry sum/sumsq stats in registers across tiles (single
// flush at kernel end); only L2's K-max is reduced per tile.
template <int L>
__global__ void __launch_bounds__(256, (L == 2) ? 2 : 3)
layer_kernel(const float* __restrict__ bias,
             const float* __restrict__ gprev,
             const float* __restrict__ beprev,
             const float* __restrict__ xyz,
             const float* __restrict__ newxyz) {
    constexpr int KIN   = (L == 0) ? 67 : 64;
    constexpr int KP    = (L == 0) ? 72 : 64;
    constexpr int NOUT  = (L == 2) ? 128 : 64;
    constexpr int XPs   = KP + 4;
    constexpr int WP2   = NOUT + 4;
    constexpr int NT    = 256;
    constexpr int NJ    = NOUT / 16;               // n-tiles per warp (4 or 8)
    constexpr int WOFF  = (L == 0) ? 0 : (L == 1) ? 72*64 : 72*64 + 64*64;
    constexpr int SOFF  = (L == 0) ? 0 : (L == 1) ? 128 : 256;
    constexpr int CSOFF = (L == 1) ? 0 : 128;
    constexpr int GRID  = (L == 2) ? (NSM * 2) : (NSM * 3);

    extern __shared__ __align__(16) float dynsmem[];
    float* Xs  = dynsmem;                          // [64][XPs]
    uint2* Ws2 = (uint2*)(dynsmem + 64 * XPs);     // [KP][WP2]

    __shared__ float    s_sc[64], s_sh[64];
    __shared__ unsigned s_max[(L == 2) ? 256 : 1];

    const int t = threadIdx.x;

    for (int i = t; i < KP * NOUT; i += NT) {
        int c = i / NOUT, o = i - c * NOUT;
        Ws2[c * WP2 + o] = g_wsplit[WOFF + i];
    }
    if (L > 0) {
        for (int i = t; i < 64; i += NT) {
            const float inv = 1.0f / (float)NROWS;
            float mean = g_stats[CSOFF + i] * inv;
            float var  = g_stats[CSOFF + 64 + i] * inv - mean * mean;
            float sc = gprev[i] * rsqrtf(var + 1e-5f);
            s_sc[i] = sc;
            s_sh[i] = beprev[i] - mean * sc;
        }
    }
    if (L == 0)
        for (int i = t; i < 64 * (KP - KIN); i += NT) {
            int r = i / (KP - KIN), c = i % (KP - KIN);
            Xs[r * XPs + KIN + c] = 0.0f;
        }

    const int lane = t & 31;
    const int wid  = t >> 5;
    const int g  = lane >> 2;
    const int tg = lane & 3;
    const int wr0 = (wid & 3) * 16;
    const int wo0 = (wid >> 2) * (NOUT / 2);

    float bb0[NJ], bb1[NJ];
    #pragma unroll
    for (int j = 0; j < NJ; j++) {
        int oc = wo0 + j * 8 + 2 * tg;
        bb0[j] = __ldg(&bias[oc]);
        bb1[j] = __ldg(&bias[oc + 1]);
    }
    float rsum[2 * NJ], rsq[2 * NJ];
    #pragma unroll
    for (int v = 0; v < 2 * NJ; v++) { rsum[v] = 0.0f; rsq[v] = 0.0f; }

    // prefetch: 64 rows x 64 cols; 256 threads x 4 float4
    float4 pf[4];
    float  pxyz[3];
    const int pr = t >> 2;            // row 0..63
    const int c0 = (t & 3) * 16;      // col part

    auto prefetch = [&](int tile_) {
        if (L == 0) {
            int row = tile_ * 64 + pr;
            int pidx = g_gidx[row];
            int b = row >> 15;
            const float4* src = (const float4*)(g_ptsT +
                ((size_t)(b * NPTS + pidx)) * 64 + c0);
            #pragma unroll
            for (int q = 0; q < 4; q++) pf[q] = __ldg(src + q);
            if (t < 64) {
                int row2 = tile_ * 64 + t;
                int pidx2 = g_gidx[row2];
                int b2 = row2 >> 15, gg = row2 >> 5;
                #pragma unroll
                for (int d = 0; d < 3; d++)
                    pxyz[d] = __ldg(&xyz[((size_t)(b2 * NPTS + pidx2)) * 3 + d])
                            - __ldg(&newxyz[gg * 3 + d]);
            }
        } else {
            const float* prev = (L == 1) ? g_y1 : g_y2;
            const float4* src = (const float4*)(prev +
                (size_t)(tile_ * 64 + pr) * 64 + c0);
            #pragma unroll
            for (int q = 0; q < 4; q++) pf[q] = __ldg(src + q);
        }
    };

    prefetch(blockIdx.x);

    for (int tile = blockIdx.x; tile < NTILES; tile += GRID) {
        __syncthreads();
        if (L == 0) {
            float* xr = Xs + pr * XPs + c0;
            #pragma unroll
            for (int q = 0; q < 4; q++) ((float4*)xr)[q] = pf[q];
            if (t < 64) {
                Xs[t * XPs + 64] = pxyz[0];
                Xs[t * XPs + 65] = pxyz[1];
                Xs[t * XPs + 66] = pxyz[2];
            }
        } else {
            #pragma unroll
            for (int q = 0; q < 4; q++) {
                int c = c0 + 4 * q;
                float4 v = pf[q];
                float4 sc4 = *(const float4*)&s_sc[c];
                float4 sh4 = *(const float4*)&s_sh[c];
                v.x = fmaxf(fmaf(v.x, sc4.x, sh4.x), 0.0f);
                v.y = fmaxf(fmaf(v.y, sc4.y, sh4.y), 0.0f);
                v.z = fmaxf(fmaf(v.z, sc4.z, sh4.z), 0.0f);
                v.w = fmaxf(fmaf(v.w, sc4.w, sh4.w), 0.0f);
                *(float4*)&Xs[pr * XPs + c] = v;
            }
        }
        if (L == 2)
            for (int i = t; i < 256; i += NT) s_max[i] = 0u;
        __syncthreads();

        int next = tile + GRID;
        if (next < NTILES) prefetch(next);

        float acc[NJ][4];
        #pragma unroll
        for (int j = 0; j < NJ; j++)
            #pragma unroll
            for (int q = 0; q < 4; q++) acc[j][q] = 0.0f;

        #pragma unroll
        for (int ks = 0; ks < KP / 8; ks++) {
            const int k0 = ks * 8;
            uint32_t ah[4], al[4];
            {
                float a0 = Xs[(wr0 + g    ) * XPs + k0 + tg];
                float a1 = Xs[(wr0 + g + 8) * XPs + k0 + tg];
                float a2 = Xs[(wr0 + g    ) * XPs + k0 + tg + 4];
                float a3 = Xs[(wr0 + g + 8) * XPs + k0 + tg + 4];
                tf32_split(a0, ah[0], al[0]);
                tf32_split(a1, ah[1], al[1]);
                tf32_split(a2, ah[2], al[2]);
                tf32_split(a3, ah[3], al[3]);
            }
            const int bbase0 = (k0 + tg) * WP2 + wo0 + g;
            const int bbase1 = (k0 + tg + 4) * WP2 + wo0 + g;
            #pragma unroll
            for (int j = 0; j < NJ; j++) {
                uint2 b0 = Ws2[bbase0 + j * 8];
                uint2 b1 = Ws2[bbase1 + j * 8];
                mma16n8k8(acc[j], ah, b0.x, b1.x);   // hh
                mma16n8k8(acc[j], al, b0.x, b1.x);   // lh
                mma16n8k8(acc[j], ah, b0.y, b1.y);   // hl
            }
        }

        const int row0 = tile * 64;
        if (L < 2) {
            float* outy = (L == 0) ? g_y1 : g_y2;
            #pragma unroll
            for (int j = 0; j < NJ; j++) {
                int oc = wo0 + j * 8 + 2 * tg;
                float v00 = acc[j][0] + bb0[j], v01 = acc[j][1] + bb1[j];
                float v10 = acc[j][2] + bb0[j], v11 = acc[j][3] + bb1[j];
                rsum[2*j]   += v00 + v10;
                rsum[2*j+1] += v01 + v11;
                rsq[2*j]   = fmaf(v00, v00, rsq[2*j]);
                rsq[2*j]   = fmaf(v10, v10, rsq[2*j]);
                rsq[2*j+1] = fmaf(v01, v01, rsq[2*j+1]);
                rsq[2*j+1] = fmaf(v11, v11, rsq[2*j+1]);
                *(float2*)&outy[(size_t)(row0 + wr0 + g    ) * NOUT + oc] =
                    make_float2(v00, v01);
                *(float2*)&outy[(size_t)(row0 + wr0 + g + 8) * NOUT + oc] =
                    make_float2(v10, v11);
            }
        } else {
            const unsigned full = 0xffffffffu;
            #pragma unroll
            for (int j = 0; j < NJ; j++) {
                int oc = wo0 + j * 8 + 2 * tg;
                float v00 = acc[j][0] + bb0[j], v01 = acc[j][1] + bb1[j];
                float v10 = acc[j][2] + bb0[j], v11 = acc[j][3] + bb1[j];
                // stats: registers, deferred to kernel end (no per-tile shfls)
                rsum[2*j]   += v00 + v10;
                rsum[2*j+1] += v01 + v11;
                rsq[2*j]   = fmaf(v00, v00, rsq[2*j]);
                rsq[2*j]   = fmaf(v10, v10, rsq[2*j]);
                rsq[2*j+1] = fmaf(v01, v01, rsq[2*j+1]);
                rsq[2*j+1] = fmaf(v11, v11, rsq[2*j+1]);
                // K-max: shfl-reduce over g lanes, then atomicMax (g==0 only)
                float m0 = fmaxf(v00, v10), m1 = fmaxf(v01, v11);
                #pragma unroll
                for (int off = 4; off < 32; off <<= 1) {
                    m0 = fmaxf(m0, __shfl_xor_sync(full, m0, off));
                    m1 = fmaxf(m1, __shfl_xor_sync(full, m1, off));
                }
                if (g == 0) {
                    int grp = (wr0 >= 32);
                    atomicMax(&s_max[grp * 128 + oc],     enc_f(m0));
                    atomicMax(&s_max[grp * 128 + oc + 1], enc_f(m1));
                }
            }
            __syncthreads();
            for (int i = t; i < 256; i += NT) {
                int grp = i >> 7, o = i & 127;
                g_ymax[(size_t)(tile * 2 + grp) * 128 + o] = dec_f(s_max[i]);
            }
        }
    }

    // ---- stats flush (all layers) ----
    {
        const unsigned full = 0xffffffffu;
        #pragma unroll
        for (int v = 0; v < 2 * NJ; v++) {
            #pragma unroll
            for (int off = 4; off < 32; off <<= 1) {
                rsum[v] += __shfl_xor_sync(full, rsum[v], off);
                rsq[v]  += __shfl_xor_sync(full, rsq[v],  off);
            }
        }
        if (g == 0) {
            #pragma unroll
            for (int j = 0; j < NJ; j++) {
                int oc = wo0 + j * 8 + 2 * tg;
                atomicAdd(&g_stats[SOFF + oc],            rsum[2*j]);
                atomicAdd(&g_stats[SOFF + oc + 1],        rsum[2*j+1]);
                atomicAdd(&g_stats[SOFF + NOUT + oc],     rsq[2*j]);
                atomicAdd(&g_stats[SOFF + NOUT + oc + 1], rsq[2*j+1]);
            }
        }
    }
}

// ---------------- finalize: bn+relu on maxima, transposed write -------------
__global__ void finalize_kernel(float* __restrict__ outp,
                                const float* __restrict__ g2,
                                const float* __restrict__ be2) {
    __shared__ float tile[32][129];
    int o0 = blockIdx.x * 32;
    int s0 = blockIdx.y * 128;
    int b  = blockIdx.z;
    int tx = threadIdx.x, ty = threadIdx.y;

    int o = o0 + tx;
    const float inv = 1.0f / (float)NROWS;
    float mean = g_stats[256 + o] * inv;
    float var  = g_stats[384 + o] * inv - mean * mean;
    float sc = g2[o] * rsqrtf(var + 1e-5f);
    float sh = be2[o] - mean * sc;

    for (int ss = ty; ss < 128; ss += 8) {
        float v = g_ymax[(size_t)(b * SPTS + s0 + ss) * 128 + o];
        tile[tx][ss] = fmaxf(fmaf(v, sc, sh), 0.0f);
    }
    __syncthreads();
    for (int oo = ty; oo < 32; oo += 8) {
        #pragma unroll
        for (int c = 0; c < 4; c++) {
            outp[((size_t)(b * 128 + o0 + oo)) * SPTS + s0 + c * 32 + tx] =
                tile[oo][c * 32 + tx];
        }
    }
}

// ---------------- launch ----------------------------------------------------
extern "C" void kernel_launch(void* const* d_in, const int* in_sizes, int n_in,
                              void* d_out, int out_size) {
    (void)in_sizes; (void)n_in; (void)out_size;
    const float* xyz = (const float*)d_in[0];
    const float* pts = (const float*)d_in[1];
    const float* w0 = (const float*)d_in[2];
    const float* b0 = (const float*)d_in[3];
    const float* g0 = (const float*)d_in[4];
    const float* be0 = (const float*)d_in[5];
    const float* w1 = (const float*)d_in[6];
    const float* b1 = (const float*)d_in[7];
    const float* g1 = (const float*)d_in[8];
    const float* be1 = (const float*)d_in[9];
    const float* w2 = (const float*)d_in[10];
    const float* b2 = (const float*)d_in[11];
    const float* g2 = (const float*)d_in[12];
    const float* be2 = (const float*)d_in[13];

    float* out = (float*)d_out;
    float* newxyz = out;                       // (B, SPTS, 3)
    float* outpts = out + OUT_XYZ_ELEMS;       // (B, 128, SPTS)

    const int L0_SMEM = (64 * 76) * 4 + (72 * 68) * 8;   // 58624
    const int L1_SMEM = (64 * 68) * 4 + (64 * 68) * 8;   // 52224
    const int L2_SMEM = (64 * 68) * 4 + (64 * 132) * 8;  // 84992
    cudaFuncSetAttribute(layer_kernel<0>,
                         cudaFuncAttributeMaxDynamicSharedMemorySize, L0_SMEM);
    cudaFuncSetAttribute(layer_kernel<1>,
                         cudaFuncAttributeMaxDynamicSharedMemorySize, L1_SMEM);
    cudaFuncSetAttribute(layer_kernel<2>,
                         cudaFuncAttributeMaxDynamicSharedMemorySize, L2_SMEM);

    // launches: fused, bq, layer0, layer1, layer2 (<- watch), finalize
    fps_fused_kernel<<<BATCH + NTILES / 2, 512>>>(xyz, pts, w0, w1, w2, newxyz);
    ballquery_kernel<<<(BATCH * SPTS) / 8, 256>>>(xyz, newxyz);

    layer_kernel<0><<<NSM * 3, 256, L0_SMEM>>>(b0, nullptr, nullptr, xyz, newxyz);
    layer_kernel<1><<<NSM * 3, 256, L1_SMEM>>>(b1, g0, be0, xyz, newxyz);
    layer_kernel<2><<<NSM * 2, 256, L2_SMEM>>>(b2, g1, be1, xyz, newxyz);

    finalize_kernel<<<dim3(4, 8, BATCH), dim3(32, 8)>>>(outpts, g2, be2);
}